// round 6
// baseline (speedup 1.0000x reference)
#include <cuda_runtime.h>
#include <cuda_bf16.h>
#include <stdint.h>

// out[b] = sum_{s=0}^{199} w_weight[text[s,b]] + bias
// text (200, 2048) row-major, tokens in [0, 50000)
#define S_TOK 200
#define B_PHR 2048
#define V_SZ  50000
#define V_HALF 25000                   // floats per rank
#define HALF_BYTES (V_HALF * 4)        // 100000 B (16B multiple)
#define CHUNK_BYTES 50000
#define PHR_PER_GRP 32                 // phrases per cluster pair
#define NBLK (2 * (B_PHR / PHR_PER_GRP))   // 128 CTAs, cluster=2
#define NTHR 1024
#define NGRP 32                        // s-groups
#define RED_FLOATS (NGRP * PHR_PER_GRP)    // 1024

// smem layout (floats): [V_HALF table][RED partials][32 partner slot][mbar pad]
#define SMEM_FLOATS (V_HALF + RED_FLOATS + 32 + 8)
#define SMEM_BYTES  (SMEM_FLOATS * 4)

__device__ __forceinline__ uint32_t smem_u32(const void* p) {
    uint32_t a;
    asm("{ .reg .u64 t; cvta.to.shared.u64 t, %1; cvt.u32.u64 %0, t; }"
        : "=r"(a) : "l"(p));
    return a;
}

__global__ __launch_bounds__(NTHR, 1) __cluster_dims__(2, 1, 1)
void MNB_455266533601_kernel(
    const void* __restrict__ text_raw,
    const float* __restrict__ w_weight,
    const float* __restrict__ w_bias,
    float* __restrict__ out)
{
    extern __shared__ float smem[];
    float* sw      = smem;                         // [V_HALF] staged half-table
    float* red     = smem + V_HALF;                // [NGRP][PHR_PER_GRP]
    float* partner = smem + V_HALF + RED_FLOATS;   // [32] rank1's partials land here (rank0)
    unsigned long long* mbar =
        (unsigned long long*)(smem + V_HALF + RED_FLOATS + 32);

    const int tid = threadIdx.x;
    const int p   = tid & (PHR_PER_GRP - 1);   // phrase within group (0..31)
    const int g   = tid >> 5;                  // s-group (0..31)

    uint32_t rank;
    asm("mov.u32 %0, %%cluster_ctarank;" : "=r"(rank));
    const int grp = blockIdx.x >> 1;           // cluster pair index
    const int b   = grp * PHR_PER_GRP + p;
    const int vlo = (int)rank * V_HALF;        // vocab range [vlo, vlo+V_HALF)

    const uint32_t mbar_a = smem_u32(mbar);

    if (tid == 0) {
        asm volatile("mbarrier.init.shared.b64 [%0], 1;" :: "r"(mbar_a) : "memory");
    }
    __syncthreads();

    // ---- async bulk fill of THIS rank's vocab half (100KB) ----
    if (tid == 0) {
        asm volatile("mbarrier.arrive.expect_tx.shared.b64 _, [%0], %1;"
                     :: "r"(mbar_a), "r"((uint32_t)HALF_BYTES) : "memory");
        uint32_t dst = smem_u32(sw);
        const char* src = (const char*)(w_weight + vlo);
#pragma unroll
        for (int c = 0; c < 2; c++) {
            asm volatile(
                "cp.async.bulk.shared::cta.global.mbarrier::complete_tx::bytes "
                "[%0], [%1], %2, [%3];"
                :: "r"(dst + c * CHUNK_BYTES),
                   "l"(src + c * CHUNK_BYTES),
                   "r"((uint32_t)CHUNK_BYTES),
                   "r"(mbar_a)
                : "memory");
        }
    }

    // ---- dtype detection (int64 buffers have zero odd 32-bit words) ----
    const unsigned int* __restrict__ t32 = (const unsigned int*)text_raw;
    unsigned int probe = t32[2 * (tid & 31) + 1];
    const bool is64 = __all_sync(0xffffffffu, probe == 0u);

    // s-groups 0..7 take 7 tokens, 8..31 take 6  (8*7 + 24*6 = 200)
    const int cnt = (g < 8) ? 7 : 6;
    const int s0  = (g < 8) ? g * 7 : 56 + (g - 8) * 6;

    // ---- coalesced index loads, overlapped with the TMA fill ----
    int idx[7];
    if (is64) {
        const long long* __restrict__ t = (const long long*)text_raw;
#pragma unroll
        for (int i = 0; i < 7; i++)
            if (i < cnt) idx[i] = (int)t[(size_t)(s0 + i) * B_PHR + b];
    } else {
        const int* __restrict__ t = (const int*)text_raw;
#pragma unroll
        for (int i = 0; i < 7; i++)
            if (i < cnt) idx[i] = t[(s0 + i) * B_PHR + b];
    }

    // ---- wait for the half-table ----
    {
        uint32_t done;
        asm volatile(
            "{\n\t.reg .pred P;\n\t"
            "mbarrier.try_wait.parity.acquire.cta.shared::cta.b64 P, [%1], 0;\n\t"
            "selp.b32 %0, 1, 0, P;\n\t}"
            : "=r"(done) : "r"(mbar_a) : "memory");
        if (!done) {
            asm volatile(
                "{\n\t.reg .pred P;\n\t"
                "WL_%=:\n\t"
                "mbarrier.try_wait.parity.acquire.cta.shared::cta.b64 P, [%0], 0, 0x989680;\n\t"
                "@P bra.uni WD_%=;\n\t"
                "bra.uni WL_%=;\n\t"
                "WD_%=:\n\t}"
                :: "r"(mbar_a) : "memory");
        }
    }

    // ---- gather in-range tokens from the staged half ----
    float acc = 0.0f;
#pragma unroll
    for (int i = 0; i < 7; i++) {
        if (i < cnt) {
            unsigned int off = (unsigned int)(idx[i] - vlo);
            if (off < (unsigned int)V_HALF) acc += sw[off];
        }
    }

    // ---- local reduce: 32 partials per phrase ----
    red[g * PHR_PER_GRP + p] = acc;
    __syncthreads();

    float own = 0.0f;
    if (tid < PHR_PER_GRP) {
#pragma unroll
        for (int j = 0; j < NGRP; j++) own += red[j * PHR_PER_GRP + tid];
        if (rank == 1) {
            // ship partials to rank 0's partner slot via DSMEM
            uint32_t laddr = smem_u32(&partner[tid]);
            uint32_t raddr;
            asm volatile("mapa.shared::cluster.u32 %0, %1, %2;"
                         : "=r"(raddr) : "r"(laddr), "r"(0));
            asm volatile("st.shared::cluster.f32 [%0], %1;"
                         :: "r"(raddr), "f"(own) : "memory");
        }
    }

    // cluster barrier: orders rank1's DSMEM store before rank0's read,
    // and keeps rank0's smem alive until the store lands.
    asm volatile("barrier.cluster.arrive.aligned;" ::: "memory");
    asm volatile("barrier.cluster.wait.aligned;" ::: "memory");

    if (rank == 0 && tid < PHR_PER_GRP) {
        out[grp * PHR_PER_GRP + tid] = own + partner[tid] + __ldg(w_bias);
    }
}

extern "C" void kernel_launch(void* const* d_in, const int* in_sizes, int n_in,
                              void* d_out, int out_size) {
    const void*  text   = d_in[0];                 // (200, 2048) int32 or int64
    const float* weight = (const float*)d_in[1];   // (1, 50000) float32
    const float* bias   = (const float*)d_in[2];   // (1,) float32
    float*       out    = (float*)d_out;           // (2048, 1) float32

    cudaFuncSetAttribute(MNB_455266533601_kernel,
                         cudaFuncAttributeMaxDynamicSharedMemorySize, SMEM_BYTES);

    MNB_455266533601_kernel<<<NBLK, NTHR, SMEM_BYTES>>>(text, weight, bias, out);
}